// round 1
// baseline (speedup 1.0000x reference)
#include <cuda_runtime.h>

#define G      180
#define NA     64
#define B      27
#define RMAX   13
#define NCELL  (B*B*B)      // 19683
#define SPLIT  2
#define THREADS 256
#define NWARP  (THREADS/32)
#define AH     0.2f
#define ROF    2.5f
#define VCELLF 0.008f

// deterministic two-stage reduction scratch: [block][128]
__device__ float g_partial[NA * SPLIT * 128];

__global__ __launch_bounds__(THREADS)
void proj_kernel(const float* __restrict__ rho, const float* __restrict__ pos)
{
    const int blk  = blockIdx.x;
    const int atom = blk / SPLIT;
    const int part = blk % SPLIT;
    const int tid  = threadIdx.x;

    __shared__ int   sxm[B], sym[B], szm[B];
    __shared__ float sxs[B], sys[B], szs[B];
    __shared__ float sred[NWARP * 128];

    const float px = pos[atom*3+0];
    const float py = pos[atom*3+1];
    const float pz = pos[atom*3+2];

    if (tid < B) {
        const float cmx = rintf(px / AH);
        const float cmy = rintf(py / AH);
        const float cmz = rintf(pz / AH);
        const int cx = (int)cmx, cy = (int)cmy, cz = (int)cmz;
        const int off = tid - RMAX;
        sxm[tid] = ((cx + off) % G + G) % G;
        sym[tid] = ((cy + off) % G + G) % G;
        szm[tid] = ((cz + off) % G + G) % G;
        const float offf = (float)off;
        sxs[tid] = offf * AH - (px - AH * cmx);
        sys[tid] = offf * AH - (py - AH * cmy);
        szs[tid] = offf * AH - (pz - AH * cmz);
    }
    __syncthreads();

    float c[128];
    #pragma unroll
    for (int v = 0; v < 128; v++) c[v] = 0.0f;

    for (int idx = part * THREADS + tid; idx < NCELL; idx += SPLIT * THREADS) {
        const int i   = idx / (B * B);
        const int rem = idx - i * (B * B);
        const int j   = rem / B;
        const int k   = rem - j * B;

        const float x = sxs[i], y = sys[j], z = szs[k];
        const float r2 = x*x + y*y + z*z;
        if (r2 >= ROF * ROF || r2 < 1e-24f) continue;

        const float srho = rho[(sxm[i] * G + sym[j]) * G + szm[k]];

        const float r   = sqrtf(r2);
        const float inv = 1.0f / r;
        const float u   = ROF - r;
        const float xh = x * inv, yh = y * inv, zh = z * inv;
        const float xh2 = xh*xh, yh2 = yh*yh, zh2 = zh*zh;

        // real spherical harmonics in Cartesian form (identical to the
        // theta/phi formulation up to rounding)
        float Yv[16];
        Yv[0]  = 0.28209479177387814f;
        Yv[1]  = 0.4886025119029199f * yh;
        Yv[2]  = 0.4886025119029199f * zh;
        Yv[3]  = 0.4886025119029199f * xh;
        Yv[4]  = 1.0925484305920792f * xh * yh;
        Yv[5]  = 1.0925484305920792f * yh * zh;
        Yv[6]  = 0.31539156525252005f * (3.0f * zh2 - 1.0f);
        Yv[7]  = 1.0925484305920792f * xh * zh;
        Yv[8]  = 0.5462742152960396f * (xh2 - yh2);
        Yv[9]  = 0.5900435899266435f * yh * (3.0f * xh2 - yh2);
        Yv[10] = 2.890611442640554f  * xh * yh * zh;
        Yv[11] = 0.4570457994644658f * yh * (5.0f * zh2 - 1.0f);
        Yv[12] = 0.3731763325901154f * zh * (5.0f * zh2 - 3.0f);
        Yv[13] = 0.4570457994644658f * xh * (5.0f * zh2 - 1.0f);
        Yv[14] = 1.445305721320277f  * zh * (xh2 - yh2);
        Yv[15] = 0.5900435899266435f * xh * (xh2 - 3.0f * yh2);

        // raw radial basis times density: t[m] = rho * r^2 * u^(m+2)
        float t[8];
        float p = r2 * u * u * srho;
        #pragma unroll
        for (int m = 0; m < 8; m++) { t[m] = p; p *= u; }

        #pragma unroll
        for (int m = 0; m < 8; m++) {
            const float tm = t[m];
            #pragma unroll
            for (int q = 0; q < 16; q++)
                c[m*16 + q] = fmaf(tm, Yv[q], c[m*16 + q]);
        }
    }

    // warp reduction -> smem -> per-value sum
    const int lane = tid & 31, warp = tid >> 5;
    #pragma unroll
    for (int v = 0; v < 128; v++) {
        float x = c[v];
        x += __shfl_down_sync(0xffffffffu, x, 16);
        x += __shfl_down_sync(0xffffffffu, x, 8);
        x += __shfl_down_sync(0xffffffffu, x, 4);
        x += __shfl_down_sync(0xffffffffu, x, 2);
        x += __shfl_down_sync(0xffffffffu, x, 1);
        if (lane == 0) sred[warp * 128 + v] = x;
    }
    __syncthreads();

    if (tid < 128) {
        float s = 0.0f;
        #pragma unroll
        for (int w = 0; w < NWARP; w++) s += sred[w * 128 + tid];
        g_partial[blk * 128 + tid] = s;
    }
}

// combine SPLIT partials, apply whitening W and VCELL
__global__ __launch_bounds__(128)
void reduce_kernel(const float* __restrict__ W, float* __restrict__ out)
{
    const int atom = blockIdx.x;
    const int tid  = threadIdx.x;   // 0..127
    __shared__ float sc[128];

    float s = 0.0f;
    #pragma unroll
    for (int p = 0; p < SPLIT; p++)
        s += g_partial[(atom * SPLIT + p) * 128 + tid];
    sc[tid] = s;
    __syncthreads();

    const int n = tid >> 4;    // radial index 0..7
    const int q = tid & 15;    // angular index 0..15  (lm = l^2 + (m+l))
    float o = 0.0f;
    #pragma unroll
    for (int m = 0; m < 8; m++)
        o = fmaf(W[n * 8 + m], sc[m * 16 + q], o);
    out[atom * 128 + tid] = o * VCELLF;
}

extern "C" void kernel_launch(void* const* d_in, const int* in_sizes, int n_in,
                              void* d_out, int out_size)
{
    const float* rho = (const float*)d_in[0];   // 180^3
    const float* pos = (const float*)d_in[1];   // 64 x 3
    const float* W   = (const float*)d_in[2];   // 8 x 8
    float* out = (float*)d_out;                 // 64 x 128

    proj_kernel<<<NA * SPLIT, THREADS>>>(rho, pos);
    reduce_kernel<<<NA, 128>>>(W, out);
}